// round 16
// baseline (speedup 1.0000x reference)
#include <cuda_runtime.h>
#include <cuda_fp16.h>
#include <math.h>
#include <stdint.h>

#define B_SZ   1024
#define H_SZ   200
#define E_SZ   256
#define R_SZ   256
#define HID_SZ 512
#define LN_EPS 1e-5f

// -------------------- scratch (device globals) -----------------------------
__device__ float g_qrepr[B_SZ * E_SZ];
__device__ float g_combined[B_SZ * 4 * E_SZ];
__device__ float g_h1[B_SZ * 2 * E_SZ];
__device__ float g_lin1[B_SZ * HID_SZ];
__device__ float g_lin2[B_SZ * E_SZ];
__device__ __half g_wrel_h[E_SZ * R_SZ];
__device__ __half g_wq_h[E_SZ * E_SZ];
__device__ __half g_w1_h[(2 * E_SZ) * (4 * E_SZ)];
__device__ __half g_w2_h[E_SZ * (2 * E_SZ)];
__device__ __half g_wc_h[HID_SZ * E_SZ];

// -------------------- helpers ----------------------------------------------
__device__ __forceinline__ uint32_t smem_to_u32(const void* p) {
    uint32_t a;
    asm("{ .reg .u64 t; cvta.to.shared.u64 t, %1; cvt.u32.u64 %0, t; }"
        : "=r"(a) : "l"(p));
    return a;
}
#define SMEM_SWIZZLE_128B(o) ((o) ^ (((o) >> 3) & 0x70))

#define LDSM_X4(r, a) \
    asm volatile("ldmatrix.sync.aligned.m8n8.x4.shared.b16 {%0,%1,%2,%3}, [%4];" \
                 : "=r"((r)[0]), "=r"((r)[1]), "=r"((r)[2]), "=r"((r)[3]) \
                 : "r"(a))

#define MMA_F16(c, a, b0, b1) \
    asm volatile("mma.sync.aligned.m16n8k16.row.col.f32.f16.f16.f32 " \
                 "{%0,%1,%2,%3}, {%4,%5,%6,%7}, {%8,%9}, {%0,%1,%2,%3};" \
                 : "+f"((c)[0]), "+f"((c)[1]), "+f"((c)[2]), "+f"((c)[3]) \
                 : "r"((a)[0]), "r"((a)[1]), "r"((a)[2]), "r"((a)[3]), \
                   "r"(b0), "r"(b1))

#define CP_ASYNC_16(dst, src) \
    asm volatile("cp.async.cg.shared.global [%0], [%1], 16;" :: "r"(dst), "l"(src))
#define CP_COMMIT() asm volatile("cp.async.commit_group;")
#define CP_WAIT0()  asm volatile("cp.async.wait_group 0;")

__device__ __forceinline__ float warpReduceSum(float v) {
#pragma unroll
    for (int o = 16; o; o >>= 1) v += __shfl_xor_sync(0xffffffffu, v, o);
    return v;
}
__device__ __forceinline__ float warpReduceMax(float v) {
#pragma unroll
    for (int o = 16; o; o >>= 1) v = fmaxf(v, __shfl_xor_sync(0xffffffffu, v, o));
    return v;
}
__device__ __forceinline__ float gelu_exact(float x) {
    return 0.5f * x * (1.0f + erff(x * 0.70710678118654752f));
}
__device__ __forceinline__ int detect_mask_mode(const void* m) {
    const unsigned char* u = (const unsigned char*)m;
    const float* f = (const float*)m;
    bool is_i = true, is_f = true;
#pragma unroll
    for (int i = 0; i < 16; i++) {
        if (u[4 * i + 1] | u[4 * i + 2] | u[4 * i + 3]) is_i = false;
        float v = f[i];
        if (v != 0.0f && v != 1.0f) is_f = false;
    }
    if (is_i) return 1;
    if (is_f) return 2;
    return 0;
}
__device__ __forceinline__ float mask_val(const void* m, int idx, int mode) {
    if (mode == 1) return ((const int*)m)[idx] != 0 ? 1.f : 0.f;
    if (mode == 2) return ((const float*)m)[idx] != 0.f ? 1.f : 0.f;
    return ((const unsigned char*)m)[idx] ? 1.f : 0.f;
}
__device__ __forceinline__ uint32_t pack_hf2(float a, float b) {
    __half2 t = __floats2half2_rn(a, b);
    return *reinterpret_cast<uint32_t*>(&t);
}

// ===========================================================================
// Kernel 0: all weight fp32 -> fp16 conversions in one launch
// ===========================================================================
#define N4_WREL (E_SZ * R_SZ / 4)
#define N4_WQ   (E_SZ * E_SZ / 4)
#define N4_W1   (2 * E_SZ * 4 * E_SZ / 4)
#define N4_W2   (E_SZ * 2 * E_SZ / 4)
#define N4_WC   (HID_SZ * E_SZ / 4)
__global__ void __launch_bounds__(256) conv_all_kernel(
        const float* __restrict__ wrel, const float* __restrict__ wq,
        const float* __restrict__ w1, const float* __restrict__ w2,
        const float* __restrict__ wc,
        __half* __restrict__ drel, __half* __restrict__ dq,
        __half* __restrict__ d1, __half* __restrict__ d2,
        __half* __restrict__ dc) {
    const size_t total = N4_WREL + N4_WQ + N4_W1 + N4_W2 + N4_WC;
    size_t i = (size_t)blockIdx.x * 256 + threadIdx.x;
    const size_t stride = (size_t)gridDim.x * 256;
    for (; i < total; i += stride) {
        const float* s;
        __half* d;
        size_t off = i;
        if (off < N4_WREL)                   { s = wrel; d = drel; }
        else if ((off -= N4_WREL) < N4_WQ)   { s = wq;   d = dq;   }
        else if ((off -= N4_WQ) < N4_W1)     { s = w1;   d = d1;   }
        else if ((off -= N4_W1) < N4_W2)     { s = w2;   d = d2;   }
        else { off -= N4_W2;                   s = wc;   d = dc;   }
        float4 x = ((const float4*)s)[off];
        ((uint2*)d)[off] = make_uint2(pack_hf2(x.x, x.y), pack_hf2(x.z, x.w));
    }
}

// ===========================================================================
// Generic HMMA linear: C[M,N] = A_f32[M,K] @ W_f16[N,K]^T (+bias)
// ===========================================================================
#define HL_OA 0
#define HL_OB 16384
__global__ void __launch_bounds__(256) hmma_linear(const float* __restrict__ A,
                                                   const __half* __restrict__ W,
                                                   const float* __restrict__ bias,
                                                   float* __restrict__ C,
                                                   int M, int N, int K) {
    __shared__ char sm[16384 + 8192];
    const uint32_t smb = smem_to_u32(sm);
    const int tid = threadIdx.x;
    const int warp = tid >> 5, lane = tid & 31;
    const int wm = warp & 3, wn = warp >> 2;
    const int m0 = blockIdx.y * 128, n0 = blockIdx.x * 64;

    float acc[2][4][4];
#pragma unroll
    for (int i = 0; i < 2; i++)
#pragma unroll
        for (int j = 0; j < 4; j++)
#pragma unroll
            for (int q = 0; q < 4; q++) acc[i][j][q] = 0.f;

    for (int k0 = 0; k0 < K; k0 += 64) {
        const float* asrc = A + (size_t)m0 * K + k0;
#pragma unroll
        for (int j = 0; j < 8; j++) {
            const int idx = tid + j * 256;
            const int row = idx >> 4, c4 = idx & 15;
            float4 x = *(const float4*)(asrc + (size_t)row * K + c4 * 4);
            const int bo = SMEM_SWIZZLE_128B(row * 128 + c4 * 8);
            *(uint2*)(sm + HL_OA + bo) = make_uint2(pack_hf2(x.x, x.y), pack_hf2(x.z, x.w));
        }
        const __half* bsrc = W + (size_t)n0 * K + k0;
#pragma unroll
        for (int j = 0; j < 2; j++) {
            const int idx = tid + j * 256;
            const int row = idx >> 3, ch = idx & 7;
            const int bo = SMEM_SWIZZLE_128B(row * 128 + ch * 16);
            *(uint4*)(sm + HL_OB + bo) = *(const uint4*)(bsrc + (size_t)row * K + ch * 8);
        }
        __syncthreads();

#pragma unroll
        for (int kk = 0; kk < 4; kk++) {
            uint32_t ah[2][4];
#pragma unroll
            for (int mt = 0; mt < 2; mt++) {
                const int arow = wm * 32 + mt * 16 + (lane & 15);
                const int aoff = SMEM_SWIZZLE_128B(arow * 128 + kk * 32 + ((lane >> 4) & 1) * 16);
                LDSM_X4(ah[mt], smb + HL_OA + aoff);
            }
#pragma unroll
            for (int np = 0; np < 2; np++) {
                const int nrow = wn * 32 + np * 16 + (lane & 7) + ((lane >> 4) & 1) * 8;
                const int boff = SMEM_SWIZZLE_128B(nrow * 128 + kk * 32 + ((lane >> 3) & 1) * 16);
                uint32_t b4[4];
                LDSM_X4(b4, smb + HL_OB + boff);
#pragma unroll
                for (int mt = 0; mt < 2; mt++) {
#pragma unroll
                    for (int h = 0; h < 2; h++)
                        MMA_F16(acc[mt][np * 2 + h], ah[mt], b4[2 * h], b4[2 * h + 1]);
                }
            }
        }
        __syncthreads();
    }

    const int g = lane >> 2, tig = lane & 3;
#pragma unroll
    for (int mt = 0; mt < 2; mt++) {
        const int r0 = m0 + wm * 32 + mt * 16 + g;
        const int r1 = r0 + 8;
#pragma unroll
        for (int j = 0; j < 4; j++) {
            const int col = n0 + wn * 32 + j * 8 + tig * 2;
            float bx = 0.f, by = 0.f;
            if (bias) { bx = bias[col]; by = bias[col + 1]; }
            *(float2*)(C + (size_t)r0 * N + col) =
                make_float2(acc[mt][j][0] + bx, acc[mt][j][1] + by);
            *(float2*)(C + (size_t)r1 * N + col) =
                make_float2(acc[mt][j][2] + bx, acc[mt][j][3] + by);
        }
    }
}

// ===========================================================================
// LayerNorm (+ optional exact GELU)
// ===========================================================================
__global__ void ln_act_kernel(const float* __restrict__ src, const float* __restrict__ gg,
                              const float* __restrict__ bb, float* __restrict__ dst,
                              int N, int do_gelu) {
    __shared__ float s_red[16];
    __shared__ float s_b;
    const int b = blockIdx.x, tid = threadIdx.x;
    const int wid = tid >> 5, lane = tid & 31;
    const int nw = blockDim.x >> 5;
    float x = src[(size_t)b * N + tid];
    float s = warpReduceSum(x);
    if (lane == 0) s_red[wid] = s;
    __syncthreads();
    if (tid < 32) {
        float t = (lane < nw) ? s_red[lane] : 0.f;
        t = warpReduceSum(t);
        if (lane == 0) s_b = t;
    }
    __syncthreads();
    const float mu = s_b / N;
    const float d = x - mu;
    float s2 = warpReduceSum(d * d);
    if (lane == 0) s_red[wid] = s2;
    __syncthreads();
    if (tid < 32) {
        float t = (lane < nw) ? s_red[lane] : 0.f;
        t = warpReduceSum(t);
        if (lane == 0) s_b = t;
    }
    __syncthreads();
    const float var = s_b / N;
    float y = d * rsqrtf(var + LN_EPS) * gg[tid] + bb[tid];
    dst[(size_t)b * N + tid] = do_gelu ? gelu_exact(y) : y;
}

// ===========================================================================
// FUSED kernel: per-batch messages GEMM + attention + PNA aggregation.
// grid = B (one CTA per batch), 256 thr (8 warps: 2m x 4n, warp 32x64).
// m-chunks of 64 rows x 4 k-stages = 16 pipelined stages; msgs live in smem.
// smem layout (dynamic):
//   [0, 105600)        msgs fp16, 200 rows x 528B (264 halfs; 256 used; pad)
//   [105600, +16384)   A tiles (2 x 8192 : 64 rows x 128B)
//   [121984, +65536)   B tiles (2 x 32768 : 256 rows x 128B)
//   [187520, +1024)    q (256 f32)
//   [188544, +1024)    logits (256 f32, 200 used)
//   [189568, +1024)    mask (256 f32)
//   [190592, +64)      reductions
// ===========================================================================
#define MROW      528
#define FO_MSG    0
#define FO_A      105600
#define FO_B      121984
#define FO_Q      187520
#define FO_LOG    188544
#define FO_MASK   189568
#define FO_RED    190592
#define SM_FUSED  190656

__global__ void __launch_bounds__(256, 1) fused_msgs_agg(
        const float* __restrict__ rel, const float* __restrict__ ent,
        const float* __restrict__ e_emb,
        const int* __restrict__ htime, const int* __restrict__ qtime,
        const void* __restrict__ maskp, const float* __restrict__ log_gamma) {
    extern __shared__ char sm[];
    const uint32_t smb = smem_to_u32(sm);
    const int tid = threadIdx.x;
    const int warp = tid >> 5, lane = tid & 31;
    const int wm = warp >> 2, wn = warp & 3;       // 2m x 4n
    const int b = blockIdx.x;
    const size_t row_base = (size_t)b * H_SZ;      // first global msg row
    const size_t row_last = (size_t)B_SZ * H_SZ - 1;

    float* s_q     = (float*)(sm + FO_Q);
    float* s_logit = (float*)(sm + FO_LOG);
    float* s_mask  = (float*)(sm + FO_MASK);
    float* s_red   = (float*)(sm + FO_RED);        // [8] + b0,b1,b2 + mode

    s_q[tid] = g_qrepr[b * E_SZ + tid];
    s_logit[tid] = 0.f;

    const char* wp = (const char*)g_wrel_h;

    // loader index components
    const int a_row = tid >> 4;                    // 0..15 (+16*j)
    const int a_c4  = tid & 15;
    const int b_row = tid >> 3;                    // 0..31 (+32*j)
    const int b_ch  = tid & 7;

    float acc[2][8][4];
#pragma unroll
    for (int i = 0; i < 2; i++)
#pragma unroll
        for (int j = 0; j < 8; j++)
#pragma unroll
            for (int q = 0; q < 4; q++) acc[i][j][q] = 0.f;

    float4 ra[4];
    const int g = lane >> 2, tig = lane & 3;

    // ---- prologue: stage 0 (chunk 0, k 0) ----------------------------------
    {
#pragma unroll
        for (int j = 0; j < 4; j++) {
            size_t grow = row_base + (a_row + j * 16);
            ra[j] = *(const float4*)(rel + grow * R_SZ + a_c4 * 4);
        }
#pragma unroll
        for (int j = 0; j < 8; j++) {
            const int row = b_row + j * 32;
            const uint32_t dst = smb + FO_B + SMEM_SWIZZLE_128B(row * 128 + b_ch * 16);
            CP_ASYNC_16(dst, wp + (size_t)row * 512 + b_ch * 16);
        }
        CP_COMMIT();
#pragma unroll
        for (int j = 0; j < 4; j++) {
            const int bo = SMEM_SWIZZLE_128B((a_row + j * 16) * 128 + a_c4 * 8);
            *(uint2*)(sm + FO_A + bo) = make_uint2(pack_hf2(ra[j].x, ra[j].y),
                                                   pack_hf2(ra[j].z, ra[j].w));
        }
        CP_WAIT0();
        __syncthreads();
    }

    for (int t = 0; t < 16; t++) {
        const int cur = t & 1, nxt = cur ^ 1;
        const int chunk = t >> 2;
        // ---- prefetch stage t+1 -------------------------------------------
        if (t < 15) {
            const int cn = (t + 1) >> 2, sn = (t + 1) & 3;
#pragma unroll
            for (int j = 0; j < 4; j++) {
                size_t grow = row_base + cn * 64 + (a_row + j * 16);
                if (grow > row_last) grow = row_last;
                ra[j] = *(const float4*)(rel + grow * R_SZ + sn * 64 + a_c4 * 4);
            }
            const size_t bk = (size_t)sn * 128;
#pragma unroll
            for (int j = 0; j < 8; j++) {
                const int row = b_row + j * 32;
                const uint32_t dst = smb + FO_B + nxt * 32768 +
                                     SMEM_SWIZZLE_128B(row * 128 + b_ch * 16);
                CP_ASYNC_16(dst, wp + bk + (size_t)row * 512 + b_ch * 16);
            }
            CP_COMMIT();
        }

        // ---- compute stage t (skip dead pad warps of chunk 3) --------------
        if (!(chunk == 3 && wm == 1)) {
            const uint32_t abuf = smb + FO_A + cur * 8192;
            const uint32_t bbuf = smb + FO_B + cur * 32768;
#pragma unroll
            for (int kk = 0; kk < 4; kk++) {
                uint32_t ah[2][4];
#pragma unroll
                for (int mt = 0; mt < 2; mt++) {
                    const int arow = wm * 32 + mt * 16 + (lane & 15);
                    const int aoff = SMEM_SWIZZLE_128B(arow * 128 + kk * 32 + ((lane >> 4) & 1) * 16);
                    LDSM_X4(ah[mt], abuf + aoff);
                }
#pragma unroll
                for (int np = 0; np < 4; np++) {
                    const int nrow = wn * 64 + np * 16 + (lane & 7) + ((lane >> 4) & 1) * 8;
                    const int boff = SMEM_SWIZZLE_128B(nrow * 128 + kk * 32 + ((lane >> 3) & 1) * 16);
                    uint32_t b4[4];
                    LDSM_X4(b4, bbuf + boff);
#pragma unroll
                    for (int mt = 0; mt < 2; mt++) {
#pragma unroll
                        for (int h = 0; h < 2; h++)
                            MMA_F16(acc[mt][np * 2 + h], ah[mt], b4[2 * h], b4[2 * h + 1]);
                    }
                }
            }
        }

        // ---- per-chunk epilogue: acc*ent -> smem msgs + logit dots ---------
        if ((t & 3) == 3) {
#pragma unroll
            for (int mt = 0; mt < 2; mt++) {
                const int lr0 = chunk * 64 + wm * 32 + mt * 16 + g;
                const int lr1 = lr0 + 8;
                const bool v0 = lr0 < H_SZ, v1 = lr1 < H_SZ;
                if (v0 || v1) {
                    const size_t rb0 = (row_base + lr0) * E_SZ;
                    const size_t rb1 = (row_base + lr1) * E_SZ;
                    float2 e1[8], e2[8];
#pragma unroll
                    for (int nt = 0; nt < 8; nt++) {
                        const int c = wn * 64 + nt * 8 + tig * 2;
                        if (v0) e1[nt] = *(const float2*)(ent + rb0 + c);
                        if (v1) e2[nt] = *(const float2*)(ent + rb1 + c);
                    }
                    float p0 = 0.f, p1 = 0.f;
#pragma unroll
                    for (int nt = 0; nt < 8; nt++) {
                        const int c = wn * 64 + nt * 8 + tig * 2;
                        if (v0) {
                            const float v00 = acc[mt][nt][0] * e1[nt].x;
                            const float v01 = acc[mt][nt][1] * e1[nt].y;
                            *(uint32_t*)(sm + FO_MSG + lr0 * MROW + c * 2) = pack_hf2(v00, v01);
                            p0 += v00 * s_q[c] + v01 * s_q[c + 1];
                        }
                        if (v1) {
                            const float v10 = acc[mt][nt][2] * e2[nt].x;
                            const float v11 = acc[mt][nt][3] * e2[nt].y;
                            *(uint32_t*)(sm + FO_MSG + lr1 * MROW + c * 2) = pack_hf2(v10, v11);
                            p1 += v10 * s_q[c] + v11 * s_q[c + 1];
                        }
                    }
                    if (v0) atomicAdd(&s_logit[lr0], p0);
                    if (v1) atomicAdd(&s_logit[lr1], p1);
                }
            }
            // reset accumulators for next chunk
#pragma unroll
            for (int i = 0; i < 2; i++)
#pragma unroll
                for (int j = 0; j < 8; j++)
#pragma unroll
                    for (int q = 0; q < 4; q++) acc[i][j][q] = 0.f;
        }

        if (t < 15) {
#pragma unroll
            for (int j = 0; j < 4; j++) {
                const int bo = SMEM_SWIZZLE_128B((a_row + j * 16) * 128 + a_c4 * 8);
                *(uint2*)(sm + FO_A + nxt * 8192 + bo) =
                    make_uint2(pack_hf2(ra[j].x, ra[j].y), pack_hf2(ra[j].z, ra[j].w));
            }
            CP_WAIT0();
        }
        __syncthreads();
    }

    // =================== attention softmax + PNA aggregation ================
    int* s_mode = (int*)(s_red + 12);
    if (tid == 0) *s_mode = detect_mask_mode(maskp);
    __syncthreads();
    const int mode = *s_mode;

    float lg = -INFINITY, mk = 0.f;
    if (tid < H_SZ) {
        mk = mask_val(maskp, b * H_SZ + tid, mode);
        s_mask[tid] = mk;
        float td = fmaxf((float)qtime[b] - (float)htime[b * H_SZ + tid], 0.f);
        float dec = expf(-expf(log_gamma[0]) * td);
        lg = (mk != 0.f) ? s_logit[tid] * dec * 0.0625f : -1e9f;
    }
    {
        float m = warpReduceMax(lg);
        if (lane == 0) s_red[warp] = m;
        __syncthreads();
        if (tid < 32) {
            float t = (lane < 8) ? s_red[lane] : -INFINITY;
            t = warpReduceMax(t);
            if (lane == 0) s_red[8] = t;
        }
        __syncthreads();
    }
    const float mx = s_red[8];
    float ex = (tid < H_SZ) ? expf(lg - mx) : 0.f;
    {
        float ss = warpReduceSum(ex);
        if (lane == 0) s_red[warp] = ss;
        __syncthreads();
        if (tid < 32) {
            float t = (lane < 8) ? s_red[lane] : 0.f;
            t = warpReduceSum(t);
            if (lane == 0) s_red[9] = t;
        }
        __syncthreads();
        float cc = warpReduceSum(mk);
        if (lane == 0) s_red[warp] = cc;
        __syncthreads();
        if (tid < 32) {
            float t = (lane < 8) ? s_red[lane] : 0.f;
            t = warpReduceSum(t);
            if (lane == 0) s_red[10] = t;
        }
        __syncthreads();
    }
    if (tid < H_SZ) s_logit[tid] = ex / s_red[9];   // reuse as weights
    __syncthreads();

    float mean = 0.f, mxv = -INFINITY, am = 0.f;
#pragma unroll 8
    for (int h = 0; h < H_SZ; h++) {
        float val = __half2float(*(const __half*)(sm + FO_MSG + h * MROW + tid * 2));
        float m = s_mask[h];
        float vm = val * m;
        mean += vm;
        mxv = fmaxf(mxv, vm);
        am += val * s_logit[h];
    }
    const float nv = fmaxf(s_red[10], 1.f);
    float* outr = g_combined + (size_t)b * 4 * E_SZ;
    outr[tid]            = mean / nv;
    outr[E_SZ + tid]     = mxv;
    outr[2 * E_SZ + tid] = am;
    outr[3 * E_SZ + tid] = e_emb[b * E_SZ + tid];
}

// ===========================================================================
extern "C" void kernel_launch(void* const* d_in, const int* in_sizes, int n_in,
                              void* d_out, int out_size) {
    const float* e_emb     = (const float*)d_in[0];
    const float* ent       = (const float*)d_in[1];
    const float* rel       = (const float*)d_in[2];
    const int*   htime     = (const int*)d_in[3];
    const int*   qtime     = (const int*)d_in[4];
    const void*  maskp     = (const void*)d_in[5];
    const float* W_rel     = (const float*)d_in[6];
    const float* W_q       = (const float*)d_in[7];
    const float* log_gamma = (const float*)d_in[8];
    const float* W1        = (const float*)d_in[9];
    const float* b1        = (const float*)d_in[10];
    const float* ln1_g     = (const float*)d_in[11];
    const float* ln1_b     = (const float*)d_in[12];
    const float* W2        = (const float*)d_in[13];
    const float* b2        = (const float*)d_in[14];
    const float* ln2_g     = (const float*)d_in[15];
    const float* ln2_b     = (const float*)d_in[16];
    const float* Wc        = (const float*)d_in[17];
    const float* bc        = (const float*)d_in[18];
    const float* lnc_g     = (const float*)d_in[19];
    const float* lnc_b     = (const float*)d_in[20];
    float* out = (float*)d_out;

    static int configured = 0;
    if (!configured) {
        cudaFuncSetAttribute(fused_msgs_agg,
                             cudaFuncAttributeMaxDynamicSharedMemorySize,
                             SM_FUSED);
        configured = 1;
    }

    __half *p_wrel, *p_wq, *p_w1, *p_w2, *p_wc;
    cudaGetSymbolAddress((void**)&p_wrel, g_wrel_h);
    cudaGetSymbolAddress((void**)&p_wq, g_wq_h);
    cudaGetSymbolAddress((void**)&p_w1, g_w1_h);
    cudaGetSymbolAddress((void**)&p_w2, g_w2_h);
    cudaGetSymbolAddress((void**)&p_wc, g_wc_h);
    float *p_qrepr, *p_comb, *p_h1, *p_lin1, *p_lin2;
    cudaGetSymbolAddress((void**)&p_qrepr, g_qrepr);
    cudaGetSymbolAddress((void**)&p_comb, g_combined);
    cudaGetSymbolAddress((void**)&p_h1, g_h1);
    cudaGetSymbolAddress((void**)&p_lin1, g_lin1);
    cudaGetSymbolAddress((void**)&p_lin2, g_lin2);

    conv_all_kernel<<<448, 256>>>(W_rel, W_q, W1, W2, Wc,
                                  p_wrel, p_wq, p_w1, p_w2, p_wc);

    // q_repr = e_emb @ W_q^T (needed by fused kernel's logits)
    hmma_linear<<<dim3(E_SZ / 64, B_SZ / 128), 256>>>(e_emb, p_wq, nullptr, p_qrepr,
                                                      B_SZ, E_SZ, E_SZ);

    // fused: messages GEMM + attention + PNA -> g_combined
    fused_msgs_agg<<<B_SZ, 256, SM_FUSED>>>(rel, ent, e_emb,
                                            htime, qtime, maskp, log_gamma);

    // MLP1
    hmma_linear<<<dim3(HID_SZ / 64, B_SZ / 128), 256>>>(p_comb, p_w1, b1, p_lin1,
                                                        B_SZ, HID_SZ, 4 * E_SZ);
    ln_act_kernel<<<B_SZ, HID_SZ>>>(p_lin1, ln1_g, ln1_b, p_h1, HID_SZ, 1);

    // MLP2 -> dyn_emb in out[0 .. B*E)
    hmma_linear<<<dim3(E_SZ / 64, B_SZ / 128), 256>>>(p_h1, p_w2, b2, p_lin2,
                                                      B_SZ, E_SZ, HID_SZ);
    ln_act_kernel<<<B_SZ, E_SZ>>>(p_lin2, ln2_g, ln2_b, out, E_SZ, 0);

    // CTX -> out[B*E ..)
    hmma_linear<<<dim3(HID_SZ / 64, B_SZ / 128), 256>>>(out, p_wc, bc, p_lin1,
                                                        B_SZ, HID_SZ, E_SZ);
    ln_act_kernel<<<B_SZ, HID_SZ>>>(p_lin1, lnc_g, lnc_b,
                                    out + (size_t)B_SZ * E_SZ, HID_SZ, 1);
}

// round 17
// speedup vs baseline: 1.3312x; 1.3312x over previous
#include <cuda_runtime.h>
#include <cuda_fp16.h>
#include <math.h>
#include <stdint.h>

#define B_SZ   1024
#define H_SZ   200
#define E_SZ   256
#define R_SZ   256
#define HID_SZ 512
#define LN_EPS 1e-5f

// -------------------- scratch (device globals) -----------------------------
__device__ __half g_msgs_h[(size_t)B_SZ * H_SZ * E_SZ];   // 104.9 MB fp16
__device__ float g_logits[B_SZ * H_SZ];
__device__ float g_qrepr[B_SZ * E_SZ];
__device__ float g_combined[B_SZ * 4 * E_SZ];
__device__ float g_h1[B_SZ * 2 * E_SZ];
__device__ float g_lin1[B_SZ * HID_SZ];
__device__ float g_lin2[B_SZ * E_SZ];
__device__ __half g_wrel_h[E_SZ * R_SZ];
__device__ __half g_wq_h[E_SZ * E_SZ];
__device__ __half g_w1_h[(2 * E_SZ) * (4 * E_SZ)];
__device__ __half g_w2_h[E_SZ * (2 * E_SZ)];
__device__ __half g_wc_h[HID_SZ * E_SZ];

// -------------------- helpers ----------------------------------------------
__device__ __forceinline__ uint32_t smem_to_u32(const void* p) {
    uint32_t a;
    asm("{ .reg .u64 t; cvta.to.shared.u64 t, %1; cvt.u32.u64 %0, t; }"
        : "=r"(a) : "l"(p));
    return a;
}
#define SMEM_SWIZZLE_128B(o) ((o) ^ (((o) >> 3) & 0x70))

#define LDSM_X4(r, a) \
    asm volatile("ldmatrix.sync.aligned.m8n8.x4.shared.b16 {%0,%1,%2,%3}, [%4];" \
                 : "=r"((r)[0]), "=r"((r)[1]), "=r"((r)[2]), "=r"((r)[3]) \
                 : "r"(a))

#define MMA_F16(c, a, b0, b1) \
    asm volatile("mma.sync.aligned.m16n8k16.row.col.f32.f16.f16.f32 " \
                 "{%0,%1,%2,%3}, {%4,%5,%6,%7}, {%8,%9}, {%0,%1,%2,%3};" \
                 : "+f"((c)[0]), "+f"((c)[1]), "+f"((c)[2]), "+f"((c)[3]) \
                 : "r"((a)[0]), "r"((a)[1]), "r"((a)[2]), "r"((a)[3]), \
                   "r"(b0), "r"(b1))

#define CP_ASYNC_16(dst, src) \
    asm volatile("cp.async.cg.shared.global [%0], [%1], 16;" :: "r"(dst), "l"(src))
#define CP_COMMIT() asm volatile("cp.async.commit_group;")
#define CP_WAIT0()  asm volatile("cp.async.wait_group 0;")

__device__ __forceinline__ float warpReduceSum(float v) {
#pragma unroll
    for (int o = 16; o; o >>= 1) v += __shfl_xor_sync(0xffffffffu, v, o);
    return v;
}
__device__ __forceinline__ float warpReduceMax(float v) {
#pragma unroll
    for (int o = 16; o; o >>= 1) v = fmaxf(v, __shfl_xor_sync(0xffffffffu, v, o));
    return v;
}
__device__ __forceinline__ float gelu_exact(float x) {
    return 0.5f * x * (1.0f + erff(x * 0.70710678118654752f));
}
__device__ __forceinline__ int detect_mask_mode(const void* m) {
    const unsigned char* u = (const unsigned char*)m;
    const float* f = (const float*)m;
    bool is_i = true, is_f = true;
#pragma unroll
    for (int i = 0; i < 16; i++) {
        if (u[4 * i + 1] | u[4 * i + 2] | u[4 * i + 3]) is_i = false;
        float v = f[i];
        if (v != 0.0f && v != 1.0f) is_f = false;
    }
    if (is_i) return 1;
    if (is_f) return 2;
    return 0;
}
__device__ __forceinline__ float mask_val(const void* m, int idx, int mode) {
    if (mode == 1) return ((const int*)m)[idx] != 0 ? 1.f : 0.f;
    if (mode == 2) return ((const float*)m)[idx] != 0.f ? 1.f : 0.f;
    return ((const unsigned char*)m)[idx] ? 1.f : 0.f;
}
__device__ __forceinline__ uint32_t pack_hf2(float a, float b) {
    __half2 t = __floats2half2_rn(a, b);
    return *reinterpret_cast<uint32_t*>(&t);
}

// ===========================================================================
// Kernel 0: all weight fp32 -> fp16 conversions in one launch
// ===========================================================================
#define N4_WREL (E_SZ * R_SZ / 4)
#define N4_WQ   (E_SZ * E_SZ / 4)
#define N4_W1   (2 * E_SZ * 4 * E_SZ / 4)
#define N4_W2   (E_SZ * 2 * E_SZ / 4)
#define N4_WC   (HID_SZ * E_SZ / 4)
__global__ void __launch_bounds__(256) conv_all_kernel(
        const float* __restrict__ wrel, const float* __restrict__ wq,
        const float* __restrict__ w1, const float* __restrict__ w2,
        const float* __restrict__ wc,
        __half* __restrict__ drel, __half* __restrict__ dq,
        __half* __restrict__ d1, __half* __restrict__ d2,
        __half* __restrict__ dc) {
    const size_t total = N4_WREL + N4_WQ + N4_W1 + N4_W2 + N4_WC;
    size_t i = (size_t)blockIdx.x * 256 + threadIdx.x;
    const size_t stride = (size_t)gridDim.x * 256;
    for (; i < total; i += stride) {
        const float* s;
        __half* d;
        size_t off = i;
        if (off < N4_WREL)                   { s = wrel; d = drel; }
        else if ((off -= N4_WREL) < N4_WQ)   { s = wq;   d = dq;   }
        else if ((off -= N4_WQ) < N4_W1)     { s = w1;   d = d1;   }
        else if ((off -= N4_W1) < N4_W2)     { s = w2;   d = d2;   }
        else { off -= N4_W2;                   s = wc;   d = dc;   }
        float4 x = ((const float4*)s)[off];
        ((uint2*)d)[off] = make_uint2(pack_hf2(x.x, x.y), pack_hf2(x.z, x.w));
    }
}

// ===========================================================================
// HMMA linear v2: C[M,N] = A_f32[M,K] @ W_f16[N,K]^T (+bias)
// CTA 64(M) x 64(N), 128 thr (4 warps 2m x 2n), warp tile 32x32, BK=64.
// Double-buffered: A through registers (cvt at STS), B via cp.async.
// smem: A0@0 (8K), A1@8K, B0@16K (8K), B1@24K  => 32KB static
// ===========================================================================
__global__ void __launch_bounds__(128) hmma_linear(const float* __restrict__ A,
                                                   const __half* __restrict__ W,
                                                   const float* __restrict__ bias,
                                                   float* __restrict__ C,
                                                   int M, int N, int K) {
    __shared__ char sm[32768];
    const uint32_t smb = smem_to_u32(sm);
    const int tid = threadIdx.x;
    const int warp = tid >> 5, lane = tid & 31;
    const int wm = warp & 1, wn = warp >> 1;
    const int m0 = blockIdx.y * 64, n0 = blockIdx.x * 64;

    float acc[2][4][4];
#pragma unroll
    for (int i = 0; i < 2; i++)
#pragma unroll
        for (int j = 0; j < 4; j++)
#pragma unroll
            for (int q = 0; q < 4; q++) acc[i][j][q] = 0.f;

    const int a_row = tid >> 4;             // 0..7 (+8*j, j<8)
    const int a_c4  = tid & 15;
    const int b_row = tid >> 3;             // 0..15 (+16*j, j<4)
    const int b_ch  = tid & 7;

    const int nstage = K >> 6;
    float4 ra[8];

    // ---- prologue: stage 0 -------------------------------------------------
    {
        const float* asrc = A + (size_t)m0 * K;
#pragma unroll
        for (int j = 0; j < 8; j++)
            ra[j] = *(const float4*)(asrc + (size_t)(a_row + j * 8) * K + a_c4 * 4);
        const __half* bsrc = W + (size_t)n0 * K;
#pragma unroll
        for (int j = 0; j < 4; j++) {
            const int row = b_row + j * 16;
            const uint32_t dst = smb + 16384 + SMEM_SWIZZLE_128B(row * 128 + b_ch * 16);
            CP_ASYNC_16(dst, bsrc + (size_t)row * K + b_ch * 8);
        }
        CP_COMMIT();
#pragma unroll
        for (int j = 0; j < 8; j++) {
            const int bo = SMEM_SWIZZLE_128B((a_row + j * 8) * 128 + a_c4 * 8);
            *(uint2*)(sm + bo) = make_uint2(pack_hf2(ra[j].x, ra[j].y),
                                            pack_hf2(ra[j].z, ra[j].w));
        }
        CP_WAIT0();
        __syncthreads();
    }

    for (int s = 0; s < nstage; s++) {
        const int cur = s & 1, nxt = cur ^ 1;
        if (s + 1 < nstage) {
            const float* asrc = A + (size_t)m0 * K + (s + 1) * 64;
#pragma unroll
            for (int j = 0; j < 8; j++)
                ra[j] = *(const float4*)(asrc + (size_t)(a_row + j * 8) * K + a_c4 * 4);
            const __half* bsrc = W + (size_t)n0 * K + (s + 1) * 64;
#pragma unroll
            for (int j = 0; j < 4; j++) {
                const int row = b_row + j * 16;
                const uint32_t dst = smb + 16384 + nxt * 8192 +
                                     SMEM_SWIZZLE_128B(row * 128 + b_ch * 16);
                CP_ASYNC_16(dst, bsrc + (size_t)row * K + b_ch * 8);
            }
            CP_COMMIT();
        }

        const uint32_t abuf = smb + cur * 8192;
        const uint32_t bbuf = smb + 16384 + cur * 8192;
#pragma unroll
        for (int kk = 0; kk < 4; kk++) {
            uint32_t ah[2][4];
#pragma unroll
            for (int mt = 0; mt < 2; mt++) {
                const int arow = wm * 32 + mt * 16 + (lane & 15);
                const int aoff = SMEM_SWIZZLE_128B(arow * 128 + kk * 32 + ((lane >> 4) & 1) * 16);
                LDSM_X4(ah[mt], abuf + aoff);
            }
#pragma unroll
            for (int np = 0; np < 2; np++) {
                const int nrow = wn * 32 + np * 16 + (lane & 7) + ((lane >> 4) & 1) * 8;
                const int boff = SMEM_SWIZZLE_128B(nrow * 128 + kk * 32 + ((lane >> 3) & 1) * 16);
                uint32_t b4[4];
                LDSM_X4(b4, bbuf + boff);
#pragma unroll
                for (int mt = 0; mt < 2; mt++) {
#pragma unroll
                    for (int h = 0; h < 2; h++)
                        MMA_F16(acc[mt][np * 2 + h], ah[mt], b4[2 * h], b4[2 * h + 1]);
                }
            }
        }

        if (s + 1 < nstage) {
#pragma unroll
            for (int j = 0; j < 8; j++) {
                const int bo = SMEM_SWIZZLE_128B((a_row + j * 8) * 128 + a_c4 * 8);
                *(uint2*)(sm + nxt * 8192 + bo) =
                    make_uint2(pack_hf2(ra[j].x, ra[j].y), pack_hf2(ra[j].z, ra[j].w));
            }
            CP_WAIT0();
        }
        __syncthreads();
    }

    const int g = lane >> 2, tig = lane & 3;
#pragma unroll
    for (int mt = 0; mt < 2; mt++) {
        const int r0 = m0 + wm * 32 + mt * 16 + g;
        const int r1 = r0 + 8;
#pragma unroll
        for (int j = 0; j < 4; j++) {
            const int col = n0 + wn * 32 + j * 8 + tig * 2;
            float bx = 0.f, by = 0.f;
            if (bias) { bx = bias[col]; by = bias[col + 1]; }
            *(float2*)(C + (size_t)r0 * N + col) =
                make_float2(acc[mt][j][0] + bx, acc[mt][j][1] + by);
            *(float2*)(C + (size_t)r1 * N + col) =
                make_float2(acc[mt][j][2] + bx, acc[mt][j][3] + by);
        }
    }
}

// ===========================================================================
// LayerNorm (+ optional exact GELU), one row per block, blockDim == N
// ===========================================================================
__global__ void ln_act_kernel(const float* __restrict__ src, const float* __restrict__ gg,
                              const float* __restrict__ bb, float* __restrict__ dst,
                              int N, int do_gelu) {
    __shared__ float s_red[16];
    __shared__ float s_b;
    const int b = blockIdx.x, tid = threadIdx.x;
    const int wid = tid >> 5, lane = tid & 31;
    const int nw = blockDim.x >> 5;
    float x = src[(size_t)b * N + tid];
    float s = warpReduceSum(x);
    if (lane == 0) s_red[wid] = s;
    __syncthreads();
    if (tid < 32) {
        float t = (lane < nw) ? s_red[lane] : 0.f;
        t = warpReduceSum(t);
        if (lane == 0) s_b = t;
    }
    __syncthreads();
    const float mu = s_b / N;
    const float d = x - mu;
    float s2 = warpReduceSum(d * d);
    if (lane == 0) s_red[wid] = s2;
    __syncthreads();
    if (tid < 32) {
        float t = (lane < nw) ? s_red[lane] : 0.f;
        t = warpReduceSum(t);
        if (lane == 0) s_b = t;
    }
    __syncthreads();
    const float var = s_b / N;
    float y = d * rsqrtf(var + LN_EPS) * gg[tid] + bb[tid];
    dst[(size_t)b * N + tid] = do_gelu ? gelu_exact(y) : y;
}

// ===========================================================================
// Kernel B: messages (fp16 out) + fused attention logits, double-buffered.
// CTA = 128(M) x 256(N), BK=64, 512 thr (16 warps 4m x 4n).  [R14-proven]
// ===========================================================================
#define SM_HMMA 98304

__global__ void __launch_bounds__(512, 1) gemm_msgs_hmma(const float* __restrict__ rel,
                                                         const float* __restrict__ ent) {
    extern __shared__ char sm[];
    const uint32_t smb = smem_to_u32(sm);
    const int tid = threadIdx.x;
    const int warp = tid >> 5, lane = tid & 31;
    const int wm = warp & 3, wn = warp >> 2;
    const int m0 = blockIdx.x * 128;

    float acc[2][8][4];
#pragma unroll
    for (int i = 0; i < 2; i++)
#pragma unroll
        for (int j = 0; j < 8; j++)
#pragma unroll
            for (int q = 0; q < 4; q++) acc[i][j][q] = 0.f;

    const char* wp = (const char*)g_wrel_h;

    const int a_row = tid >> 4;
    const int a_c4  = tid & 15;
    const int b_row = tid >> 3;
    const int b_ch  = tid & 7;

    float4 ra[4];

    {
        const float* asrc = rel + (size_t)m0 * R_SZ;
#pragma unroll
        for (int j = 0; j < 4; j++)
            ra[j] = *(const float4*)(asrc + (size_t)(a_row + j * 32) * R_SZ + a_c4 * 4);
#pragma unroll
        for (int j = 0; j < 4; j++) {
            const int row = b_row + j * 64;
            const uint32_t dst = smb + 32768 + SMEM_SWIZZLE_128B(row * 128 + b_ch * 16);
            CP_ASYNC_16(dst, wp + (size_t)row * 512 + b_ch * 16);
        }
        CP_COMMIT();
#pragma unroll
        for (int j = 0; j < 4; j++) {
            const int bo = SMEM_SWIZZLE_128B((a_row + j * 32) * 128 + a_c4 * 8);
            *(uint2*)(sm + bo) = make_uint2(pack_hf2(ra[j].x, ra[j].y),
                                            pack_hf2(ra[j].z, ra[j].w));
        }
        CP_WAIT0();
        __syncthreads();
    }

#pragma unroll
    for (int s = 0; s < 4; s++) {
        const int cur = s & 1, nxt = (s + 1) & 1;
        if (s < 3) {
            const float* asrc = rel + (size_t)m0 * R_SZ + (s + 1) * 64;
#pragma unroll
            for (int j = 0; j < 4; j++)
                ra[j] = *(const float4*)(asrc + (size_t)(a_row + j * 32) * R_SZ + a_c4 * 4);
            const size_t bk = (size_t)(s + 1) * 128;
#pragma unroll
            for (int j = 0; j < 4; j++) {
                const int row = b_row + j * 64;
                const uint32_t dst = smb + 32768 + nxt * 32768 +
                                     SMEM_SWIZZLE_128B(row * 128 + b_ch * 16);
                CP_ASYNC_16(dst, wp + bk + (size_t)row * 512 + b_ch * 16);
            }
            CP_COMMIT();
        }

        const uint32_t abuf = smb + cur * 16384;
        const uint32_t bbuf = smb + 32768 + cur * 32768;
#pragma unroll
        for (int kk = 0; kk < 4; kk++) {
            uint32_t ah[2][4];
#pragma unroll
            for (int mt = 0; mt < 2; mt++) {
                const int arow = wm * 32 + mt * 16 + (lane & 15);
                const int aoff = SMEM_SWIZZLE_128B(arow * 128 + kk * 32 + ((lane >> 4) & 1) * 16);
                LDSM_X4(ah[mt], abuf + aoff);
            }
#pragma unroll
            for (int np = 0; np < 4; np++) {
                const int nrow = wn * 64 + np * 16 + (lane & 7) + ((lane >> 4) & 1) * 8;
                const int boff = SMEM_SWIZZLE_128B(nrow * 128 + kk * 32 + ((lane >> 3) & 1) * 16);
                uint32_t b4[4];
                LDSM_X4(b4, bbuf + boff);
#pragma unroll
                for (int mt = 0; mt < 2; mt++) {
#pragma unroll
                    for (int h = 0; h < 2; h++)
                        MMA_F16(acc[mt][np * 2 + h], ah[mt], b4[2 * h], b4[2 * h + 1]);
                }
            }
        }

        if (s < 3) {
#pragma unroll
            for (int j = 0; j < 4; j++) {
                const int bo = SMEM_SWIZZLE_128B((a_row + j * 32) * 128 + a_c4 * 8);
                *(uint2*)(sm + nxt * 16384 + bo) =
                    make_uint2(pack_hf2(ra[j].x, ra[j].y), pack_hf2(ra[j].z, ra[j].w));
            }
            CP_WAIT0();
        }
        __syncthreads();
    }

    // ---- logits staging (A buffers now free) -------------------------------
    float* s_logit = (float*)sm;
    float* s_qv    = (float*)(sm + 512);
    if (tid < 128) s_logit[tid] = 0.f;
    const int bA = m0 / H_SZ;
    const int bB = (m0 + 127) / H_SZ;
    {
        const int part = tid >> 8, col = tid & 255;
        const int qb = part ? bB : bA;
        s_qv[tid] = g_qrepr[qb * E_SZ + col];
    }
    __syncthreads();

    const int g = lane >> 2, tig = lane & 3;
#pragma unroll
    for (int mt = 0; mt < 2; mt++) {
        const int lr0 = wm * 32 + mt * 16 + g;
        const int lr1 = lr0 + 8;
        const float* q0 = s_qv + (((m0 + lr0) / H_SZ == bA) ? 0 : 256);
        const float* q1 = s_qv + (((m0 + lr1) / H_SZ == bA) ? 0 : 256);
        const size_t rb0 = (size_t)(m0 + lr0) * E_SZ;
        const size_t rb1 = (size_t)(m0 + lr1) * E_SZ;
        float2 e1[8], e2[8];
#pragma unroll
        for (int nt = 0; nt < 8; nt++) {
            const int c = wn * 64 + nt * 8 + tig * 2;
            e1[nt] = *(const float2*)(ent + rb0 + c);
            e2[nt] = *(const float2*)(ent + rb1 + c);
        }
        float p0 = 0.f, p1 = 0.f;
#pragma unroll
        for (int nt = 0; nt < 8; nt++) {
            const int c = wn * 64 + nt * 8 + tig * 2;
            const float v00 = acc[mt][nt][0] * e1[nt].x, v01 = acc[mt][nt][1] * e1[nt].y;
            const float v10 = acc[mt][nt][2] * e2[nt].x, v11 = acc[mt][nt][3] * e2[nt].y;
            *(uint32_t*)(g_msgs_h + rb0 + c) = pack_hf2(v00, v01);
            *(uint32_t*)(g_msgs_h + rb1 + c) = pack_hf2(v10, v11);
            p0 += v00 * q0[c] + v01 * q0[c + 1];
            p1 += v10 * q1[c] + v11 * q1[c + 1];
        }
        atomicAdd(&s_logit[lr0], p0);
        atomicAdd(&s_logit[lr1], p1);
    }
    __syncthreads();
    if (tid < 128) g_logits[m0 + tid] = s_logit[tid];
}

// ===========================================================================
// Kernel C: softmax from precomputed logits + streaming PNA reductions (fp16)
// ===========================================================================
__global__ void __launch_bounds__(256) aggregate_v2(const float* __restrict__ e_emb,
                                                    const int* __restrict__ htime,
                                                    const int* __restrict__ qtime,
                                                    const void* __restrict__ maskp,
                                                    const float* __restrict__ log_gamma) {
    __shared__ float s_w[H_SZ];
    __shared__ float s_mask[H_SZ];
    __shared__ float s_red[8];
    __shared__ float s_b0, s_b1, s_b2;
    __shared__ int s_mode;

    const int b = blockIdx.x, tid = threadIdx.x;
    const int wid = tid >> 5, lane = tid & 31;

    if (tid == 0) s_mode = detect_mask_mode(maskp);
    __syncthreads();

    float lg = -INFINITY, mk = 0.f;
    if (tid < H_SZ) {
        mk = mask_val(maskp, b * H_SZ + tid, s_mode);
        s_mask[tid] = mk;
        float raw = g_logits[b * H_SZ + tid];
        float td = fmaxf((float)qtime[b] - (float)htime[b * H_SZ + tid], 0.f);
        float dec = expf(-expf(log_gamma[0]) * td);
        lg = (mk != 0.f) ? raw * dec * 0.0625f : -1e9f;
    }
    {
        float m = warpReduceMax(lg);
        if (lane == 0) s_red[wid] = m;
        __syncthreads();
        if (tid < 32) {
            float t = (lane < 8) ? s_red[lane] : -INFINITY;
            t = warpReduceMax(t);
            if (lane == 0) s_b0 = t;
        }
        __syncthreads();
    }
    const float mx = s_b0;
    float ex = (tid < H_SZ) ? expf(lg - mx) : 0.f;
    {
        float ss = warpReduceSum(ex);
        if (lane == 0) s_red[wid] = ss;
        __syncthreads();
        if (tid < 32) {
            float t = (lane < 8) ? s_red[lane] : 0.f;
            t = warpReduceSum(t);
            if (lane == 0) s_b1 = t;
        }
        __syncthreads();
        float cc = warpReduceSum(mk);
        if (lane == 0) s_red[wid] = cc;
        __syncthreads();
        if (tid < 32) {
            float t = (lane < 8) ? s_red[lane] : 0.f;
            t = warpReduceSum(t);
            if (lane == 0) s_b2 = t;
        }
        __syncthreads();
    }
    if (tid < H_SZ) s_w[tid] = ex / s_b1;
    __syncthreads();

    const __half* base = g_msgs_h + (size_t)b * H_SZ * E_SZ + tid;
    float mean = 0.f, mxv = -INFINITY, am = 0.f;
#pragma unroll 8
    for (int h = 0; h < H_SZ; h++) {
        float val = __half2float(base[(size_t)h * E_SZ]);
        float m = s_mask[h];
        float vm = val * m;
        mean += vm;
        mxv = fmaxf(mxv, vm);
        am += val * s_w[h];
    }
    const float nv = fmaxf(s_b2, 1.f);
    float* outr = g_combined + (size_t)b * 4 * E_SZ;
    outr[tid]            = mean / nv;
    outr[E_SZ + tid]     = mxv;
    outr[2 * E_SZ + tid] = am;
    outr[3 * E_SZ + tid] = e_emb[b * E_SZ + tid];
}

// ===========================================================================
extern "C" void kernel_launch(void* const* d_in, const int* in_sizes, int n_in,
                              void* d_out, int out_size) {
    const float* e_emb     = (const float*)d_in[0];
    const float* ent       = (const float*)d_in[1];
    const float* rel       = (const float*)d_in[2];
    const int*   htime     = (const int*)d_in[3];
    const int*   qtime     = (const int*)d_in[4];
    const void*  maskp     = (const void*)d_in[5];
    const float* W_rel     = (const float*)d_in[6];
    const float* W_q       = (const float*)d_in[7];
    const float* log_gamma = (const float*)d_in[8];
    const float* W1        = (const float*)d_in[9];
    const float* b1        = (const float*)d_in[10];
    const float* ln1_g     = (const float*)d_in[11];
    const float* ln1_b     = (const float*)d_in[12];
    const float* W2        = (const float*)d_in[13];
    const float* b2        = (const float*)d_in[14];
    const float* ln2_g     = (const float*)d_in[15];
    const float* ln2_b     = (const float*)d_in[16];
    const float* Wc        = (const float*)d_in[17];
    const float* bc        = (const float*)d_in[18];
    const float* lnc_g     = (const float*)d_in[19];
    const float* lnc_b     = (const float*)d_in[20];
    float* out = (float*)d_out;

    static int configured = 0;
    if (!configured) {
        cudaFuncSetAttribute(gemm_msgs_hmma,
                             cudaFuncAttributeMaxDynamicSharedMemorySize,
                             SM_HMMA);
        configured = 1;
    }

    __half *p_wrel, *p_wq, *p_w1, *p_w2, *p_wc;
    cudaGetSymbolAddress((void**)&p_wrel, g_wrel_h);
    cudaGetSymbolAddress((void**)&p_wq, g_wq_h);
    cudaGetSymbolAddress((void**)&p_w1, g_w1_h);
    cudaGetSymbolAddress((void**)&p_w2, g_w2_h);
    cudaGetSymbolAddress((void**)&p_wc, g_wc_h);
    float *p_qrepr, *p_comb, *p_h1, *p_lin1, *p_lin2;
    cudaGetSymbolAddress((void**)&p_qrepr, g_qrepr);
    cudaGetSymbolAddress((void**)&p_comb, g_combined);
    cudaGetSymbolAddress((void**)&p_h1, g_h1);
    cudaGetSymbolAddress((void**)&p_lin1, g_lin1);
    cudaGetSymbolAddress((void**)&p_lin2, g_lin2);

    conv_all_kernel<<<448, 256>>>(W_rel, W_q, W1, W2, Wc,
                                  p_wrel, p_wq, p_w1, p_w2, p_wc);

    // q_repr = e_emb @ W_q^T  (grid 4x16 = 64 CTAs)
    hmma_linear<<<dim3(E_SZ / 64, B_SZ / 64), 128>>>(e_emb, p_wq, nullptr, p_qrepr,
                                                     B_SZ, E_SZ, E_SZ);

    gemm_msgs_hmma<<<(B_SZ * H_SZ) / 128, 512, SM_HMMA>>>(rel, ent);

    aggregate_v2<<<B_SZ, 256>>>(e_emb, htime, qtime, maskp, log_gamma);

    // MLP1  (grid 8x16 = 128 CTAs)
    hmma_linear<<<dim3(HID_SZ / 64, B_SZ / 64), 128>>>(p_comb, p_w1, b1, p_lin1,
                                                       B_SZ, HID_SZ, 4 * E_SZ);
    ln_act_kernel<<<B_SZ, HID_SZ>>>(p_lin1, ln1_g, ln1_b, p_h1, HID_SZ, 1);

    // MLP2 -> dyn_emb in out[0 .. B*E)  (grid 4x16)
    hmma_linear<<<dim3(E_SZ / 64, B_SZ / 64), 128>>>(p_h1, p_w2, b2, p_lin2,
                                                     B_SZ, E_SZ, HID_SZ);
    ln_act_kernel<<<B_SZ, E_SZ>>>(p_lin2, ln2_g, ln2_b, out, E_SZ, 0);

    // CTX -> out[B*E ..)  (grid 8x16)
    hmma_linear<<<dim3(HID_SZ / 64, B_SZ / 64), 128>>>(out, p_wc, bc, p_lin1,
                                                       B_SZ, HID_SZ, E_SZ);
    ln_act_kernel<<<B_SZ, HID_SZ>>>(p_lin1, lnc_g, lnc_b,
                                    out + (size_t)B_SZ * E_SZ, HID_SZ, 1);
}